// round 1
// baseline (speedup 1.0000x reference)
#include <cuda_runtime.h>
#include <math.h>

#define NM 1024
#define HH 256
#define WW 256
#define HW (HH * WW)

// Per-mask reduction results (scratch; allocation-free per harness rules)
__device__ int g_hi[NM];
__device__ int g_lo[NM];
__device__ int g_minr[NM];
__device__ int g_maxr[NM];
__device__ int g_minc[NM];
__device__ int g_maxc[NM];
__device__ float g_gate[NM];

// ---------------------------------------------------------------------------
// Pass 1: per-mask streaming reduction.
// One block per mask, 256 threads, each thread reads 64 float4 (256 floats).
// Computes: hi = #(x > 1), lo = #(x > -1), bbox over (x > 0).
// ---------------------------------------------------------------------------
__global__ __launch_bounds__(256) void reduce_k(const float* __restrict__ logits) {
    const int n = blockIdx.x;
    const float4* p = reinterpret_cast<const float4*>(logits) + (size_t)n * (HW / 4);
    const int tid = threadIdx.x;

    int hi = 0, lo = 0;
    int minr = HH, maxr = -1, minc = WW, maxc = -1;

#pragma unroll 4
    for (int it = 0; it < 64; ++it) {
        const int idx = it * 256 + tid;      // float4 index within mask
        const float4 v = p[idx];
        const int pix = idx << 2;            // first-element pixel index
        const int row = pix >> 8;            // W = 256
        const int col = pix & 255;

        hi += (v.x > 1.f) + (v.y > 1.f) + (v.z > 1.f) + (v.w > 1.f);
        lo += (v.x > -1.f) + (v.y > -1.f) + (v.z > -1.f) + (v.w > -1.f);

        const bool bx = v.x > 0.f, by = v.y > 0.f, bz = v.z > 0.f, bw = v.w > 0.f;
        if (bx | by | bz | bw) {
            minr = min(minr, row);
            maxr = max(maxr, row);
            const int lc = col + (bx ? 0 : (by ? 1 : (bz ? 2 : 3)));
            const int hc = col + (bw ? 3 : (bz ? 2 : (by ? 1 : 0)));
            minc = min(minc, lc);
            maxc = max(maxc, hc);
        }
    }

    // warp reduce
#pragma unroll
    for (int off = 16; off; off >>= 1) {
        hi += __shfl_down_sync(0xffffffffu, hi, off);
        lo += __shfl_down_sync(0xffffffffu, lo, off);
        minr = min(minr, __shfl_down_sync(0xffffffffu, minr, off));
        maxr = max(maxr, __shfl_down_sync(0xffffffffu, maxr, off));
        minc = min(minc, __shfl_down_sync(0xffffffffu, minc, off));
        maxc = max(maxc, __shfl_down_sync(0xffffffffu, maxc, off));
    }

    __shared__ int s[8][6];
    const int w = tid >> 5, l = tid & 31;
    if (l == 0) {
        s[w][0] = hi; s[w][1] = lo; s[w][2] = minr;
        s[w][3] = maxr; s[w][4] = minc; s[w][5] = maxc;
    }
    __syncthreads();
    if (w == 0) {
        const bool a = l < 8;
        hi   = a ? s[l][0] : 0;
        lo   = a ? s[l][1] : 0;
        minr = a ? s[l][2] : HH;
        maxr = a ? s[l][3] : -1;
        minc = a ? s[l][4] : WW;
        maxc = a ? s[l][5] : -1;
#pragma unroll
        for (int off = 16; off; off >>= 1) {
            hi += __shfl_down_sync(0xffffffffu, hi, off);
            lo += __shfl_down_sync(0xffffffffu, lo, off);
            minr = min(minr, __shfl_down_sync(0xffffffffu, minr, off));
            maxr = max(maxr, __shfl_down_sync(0xffffffffu, maxr, off));
            minc = min(minc, __shfl_down_sync(0xffffffffu, minc, off));
            maxc = max(maxc, __shfl_down_sync(0xffffffffu, maxc, off));
        }
        if (l == 0) {
            g_hi[n] = hi; g_lo[n] = lo;
            g_minr[n] = minr; g_maxr[n] = maxr;
            g_minc[n] = minc; g_maxc[n] = maxc;
        }
    }
}

// ---------------------------------------------------------------------------
// Pass 2: validity, boxes, greedy NMS over the compacted valid subset.
// Exact match to reference: invalid masks can neither be kept nor suppress,
// so NMS restricted to valid masks is equivalent. Ties broken by original
// index (stable argsort semantics); suppressed boxes do not suppress others.
// Single block of 1024 threads.
// ---------------------------------------------------------------------------
__global__ __launch_bounds__(1024) void nms_k(const float* __restrict__ iou_preds,
                                              float* __restrict__ keep_out,
                                              float* __restrict__ boxes_out,
                                              int write_keep, int write_boxes) {
    __shared__ float4 sbox[NM];
    __shared__ float  skey[NM];
    __shared__ int    svidx[NM];
    __shared__ int    ssorted[NM];
    __shared__ int    skeep[NM];
    __shared__ int    skeeporig[NM];
    __shared__ int    scnt;

    const int tid = threadIdx.x;
    if (tid == 0) scnt = 0;

    const int minr = g_minr[tid], maxr = g_maxr[tid];
    const int minc = g_minc[tid], maxc = g_maxc[tid];
    const bool empty = (maxr < 0);
    const float4 box = empty ? make_float4(0.f, 0.f, 0.f, 0.f)
                             : make_float4((float)minc, (float)minr,
                                           (float)maxc, (float)maxr);
    sbox[tid] = box;

    const float iou = iou_preds[tid];
    const float stab = (float)g_hi[tid] / fmaxf((float)g_lo[tid], 1.0f);
    const bool valid = (iou > 0.88f) && (stab >= 0.95f);
    skey[tid] = iou;
    skeeporig[tid] = 0;
    __syncthreads();

    if (valid) {
        const int p = atomicAdd(&scnt, 1);
        svidx[p] = tid;
    }
    __syncthreads();
    const int V = scnt;

    // Rank sort (descending score, tie-break by original index ascending)
    if (tid < V) {
        const int orig = svidx[tid];
        const float key = skey[orig];
        int rank = 0;
        for (int j = 0; j < V; ++j) {
            const int oj = svidx[j];
            const float kj = skey[oj];
            rank += (int)((kj > key) | ((kj == key) & (oj < orig)));
        }
        ssorted[rank] = orig;
        skeep[rank] = 1;
    }
    __syncthreads();

    float4 bj = make_float4(0.f, 0.f, 0.f, 0.f);
    float area_j = 0.f;
    if (tid < V) {
        bj = sbox[ssorted[tid]];
        area_j = fmaxf(bj.z - bj.x, 0.f) * fmaxf(bj.w - bj.y, 0.f);
    }

    // Greedy suppression, sorted order. skeep[i] writes only target idx > i,
    // so the single sync at loop top is sufficient ordering.
    for (int i = 0; i < V; ++i) {
        __syncthreads();
        if (!skeep[i]) continue;      // uniform (shared)
        if (tid > i && tid < V && skeep[tid]) {
            const float4 bi = sbox[ssorted[i]];
            const float x0 = fmaxf(bi.x, bj.x);
            const float y0 = fmaxf(bi.y, bj.y);
            const float x1 = fminf(bi.z, bj.z);
            const float y1 = fminf(bi.w, bj.w);
            const float inter = fmaxf(x1 - x0, 0.f) * fmaxf(y1 - y0, 0.f);
            const float area_i = fmaxf(bi.z - bi.x, 0.f) * fmaxf(bi.w - bi.y, 0.f);
            const float u = fmaxf(area_i + area_j - inter, 1e-6f);
            if (inter / u > 0.7f) skeep[tid] = 0;
        }
    }
    __syncthreads();

    if (tid < V && skeep[tid]) skeeporig[ssorted[tid]] = 1;
    __syncthreads();

    const int kept = skeeporig[tid];
    g_gate[tid] = kept ? iou : 0.f;
    if (write_keep) keep_out[tid] = kept ? 1.f : 0.f;
    if (write_boxes) {
        reinterpret_cast<float4*>(boxes_out)[tid] = box;
    }
}

// ---------------------------------------------------------------------------
// Pass 3: out = sigmoid(logits) * gate[n]. gate==0 (~94% of masks): write
// zeros without reading logits -> skips most of the input re-read.
// Grid (16, NM), 256 threads, 4 float4 per thread.
// ---------------------------------------------------------------------------
__global__ __launch_bounds__(256) void out_k(const float* __restrict__ logits,
                                             float* __restrict__ out) {
    const int n = blockIdx.y;
    const float g = g_gate[n];
    const size_t base4 = (size_t)n * (HW / 4) + (size_t)blockIdx.x * 1024;
    const float4* ip = reinterpret_cast<const float4*>(logits) + base4;
    float4* op = reinterpret_cast<float4*>(out) + base4;
    const int tid = threadIdx.x;

    if (g == 0.f) {
        const float4 z = make_float4(0.f, 0.f, 0.f, 0.f);
#pragma unroll
        for (int k = 0; k < 4; ++k) op[k * 256 + tid] = z;
    } else {
#pragma unroll
        for (int k = 0; k < 4; ++k) {
            const float4 v = ip[k * 256 + tid];
            float4 r;
            r.x = g * (1.f / (1.f + __expf(-v.x)));
            r.y = g * (1.f / (1.f + __expf(-v.y)));
            r.z = g * (1.f / (1.f + __expf(-v.z)));
            r.w = g * (1.f / (1.f + __expf(-v.w)));
            op[k * 256 + tid] = r;
        }
    }
}

extern "C" void kernel_launch(void* const* d_in, const int* in_sizes, int n_in,
                              void* d_out, int out_size) {
    const float* logits;
    const float* ioup;
    // Identify inputs by size (mask_logits: 64M elems, iou_preds: 1024)
    if (in_sizes[0] == NM) {
        ioup = (const float*)d_in[0];
        logits = (const float*)d_in[1];
    } else {
        logits = (const float*)d_in[0];
        ioup = (const float*)d_in[1];
    }

    float* out = (float*)d_out;
    const long long main_sz = (long long)NM * HW;
    const int wk = ((long long)out_size >= main_sz + NM) ? 1 : 0;
    const int wb = ((long long)out_size >= main_sz + NM + 4LL * NM) ? 1 : 0;
    float* keep_out = out + (size_t)NM * HW;
    float* boxes_out = keep_out + NM;

    reduce_k<<<NM, 256>>>(logits);
    nms_k<<<1, NM>>>(ioup, keep_out, boxes_out, wk, wb);
    out_k<<<dim3(16, NM), 256>>>(logits, out);
}

// round 6
// speedup vs baseline: 1.0417x; 1.0417x over previous
#include <cuda_runtime.h>
#include <math.h>

#define NM 1024
#define HH 256
#define WW 256
#define HW (HH * WW)

// Per-mask reduction results (scratch; allocation-free per harness rules)
__device__ int g_hi[NM];
__device__ int g_lo[NM];
__device__ int g_minr[NM];
__device__ int g_maxr[NM];
__device__ int g_minc[NM];
__device__ int g_maxc[NM];
__device__ float g_gate[NM];

// ---------------------------------------------------------------------------
// Pass 1 (fused): per-mask streaming reduction + zero-fill of the output.
// One block per mask, 256 threads, each thread reads 64 float4 (256 floats)
// and stores 64 zero float4s to out. The zeros are correct for all non-kept
// masks (~94%); kept masks are overwritten by pass 3.
//
// Index math: idx = it*256 + tid  ->  row = 4*it + (tid>>6), col base =
// (tid&63)*4 is FIXED per thread. So bbox tracking reduces to OR-accumulating
// a 64-bit row(it) mask and a 4-bit column-lane mask; min/max recovered via
// ffs/clz once at the end.
// ---------------------------------------------------------------------------
__global__ __launch_bounds__(256) void fused_reduce_k(const float* __restrict__ logits,
                                                      float* __restrict__ out) {
    const int n = blockIdx.x;
    const float4* p = reinterpret_cast<const float4*>(logits) + (size_t)n * (HW / 4);
    float4* o = reinterpret_cast<float4*>(out) + (size_t)n * (HW / 4);
    const int tid = threadIdx.x;

    int hi = 0, lo = 0;
    unsigned long long rowmask = 0ull;
    int colbits = 0;
    const float4 z = make_float4(0.f, 0.f, 0.f, 0.f);

#pragma unroll 4
    for (int it = 0; it < 64; ++it) {
        const int idx = it * 256 + tid;
        const float4 v = p[idx];
        o[idx] = z;

        hi += (v.x > 1.f) + (v.y > 1.f) + (v.z > 1.f) + (v.w > 1.f);
        lo += (v.x > -1.f) + (v.y > -1.f) + (v.z > -1.f) + (v.w > -1.f);

        const int b = (int)(v.x > 0.f) | ((int)(v.y > 0.f) << 1) |
                      ((int)(v.z > 0.f) << 2) | ((int)(v.w > 0.f) << 3);
        colbits |= b;
        rowmask |= (unsigned long long)(b != 0) << it;
    }

    // Recover per-thread bbox
    int minr, maxr, minc, maxc;
    if (rowmask) {
        const int rowoff = tid >> 6;
        const int cbase = (tid & 63) << 2;
        const int minIt = __ffsll((long long)rowmask) - 1;
        const int maxIt = 63 - __clzll((long long)rowmask);
        minr = 4 * minIt + rowoff;
        maxr = 4 * maxIt + rowoff;
        minc = cbase + (__ffs(colbits) - 1);
        maxc = cbase + (31 - __clz((unsigned)colbits));
    } else {
        minr = HH; maxr = -1; minc = WW; maxc = -1;
    }

    // warp reduce
#pragma unroll
    for (int off = 16; off; off >>= 1) {
        hi += __shfl_down_sync(0xffffffffu, hi, off);
        lo += __shfl_down_sync(0xffffffffu, lo, off);
        minr = min(minr, __shfl_down_sync(0xffffffffu, minr, off));
        maxr = max(maxr, __shfl_down_sync(0xffffffffu, maxr, off));
        minc = min(minc, __shfl_down_sync(0xffffffffu, minc, off));
        maxc = max(maxc, __shfl_down_sync(0xffffffffu, maxc, off));
    }

    __shared__ int s[8][6];
    const int w = tid >> 5, l = tid & 31;
    if (l == 0) {
        s[w][0] = hi; s[w][1] = lo; s[w][2] = minr;
        s[w][3] = maxr; s[w][4] = minc; s[w][5] = maxc;
    }
    __syncthreads();
    if (w == 0) {
        const bool a = l < 8;
        hi   = a ? s[l][0] : 0;
        lo   = a ? s[l][1] : 0;
        minr = a ? s[l][2] : HH;
        maxr = a ? s[l][3] : -1;
        minc = a ? s[l][4] : WW;
        maxc = a ? s[l][5] : -1;
#pragma unroll
        for (int off = 16; off; off >>= 1) {
            hi += __shfl_down_sync(0xffffffffu, hi, off);
            lo += __shfl_down_sync(0xffffffffu, lo, off);
            minr = min(minr, __shfl_down_sync(0xffffffffu, minr, off));
            maxr = max(maxr, __shfl_down_sync(0xffffffffu, maxr, off));
            minc = min(minc, __shfl_down_sync(0xffffffffu, minc, off));
            maxc = max(maxc, __shfl_down_sync(0xffffffffu, maxc, off));
        }
        if (l == 0) {
            g_hi[n] = hi; g_lo[n] = lo;
            g_minr[n] = minr; g_maxr[n] = maxr;
            g_minc[n] = minc; g_maxc[n] = maxc;
        }
    }
}

// ---------------------------------------------------------------------------
// Pass 2: validity, boxes, greedy NMS over the compacted valid subset.
// Exact match to reference: invalid masks can neither be kept nor suppress,
// so NMS restricted to valid masks is equivalent. Ties broken by original
// index (stable argsort semantics); suppressed boxes do not suppress others.
// Single block of 1024 threads.
// ---------------------------------------------------------------------------
__global__ __launch_bounds__(1024) void nms_k(const float* __restrict__ iou_preds,
                                              float* __restrict__ keep_out,
                                              float* __restrict__ boxes_out,
                                              int write_keep, int write_boxes) {
    __shared__ float4 sbox[NM];
    __shared__ float  skey[NM];
    __shared__ int    svidx[NM];
    __shared__ int    ssorted[NM];
    __shared__ int    skeep[NM];
    __shared__ int    skeeporig[NM];
    __shared__ int    scnt;

    const int tid = threadIdx.x;
    if (tid == 0) scnt = 0;

    const int minr = g_minr[tid], maxr = g_maxr[tid];
    const int minc = g_minc[tid], maxc = g_maxc[tid];
    const bool empty = (maxr < 0);
    const float4 box = empty ? make_float4(0.f, 0.f, 0.f, 0.f)
                             : make_float4((float)minc, (float)minr,
                                           (float)maxc, (float)maxr);
    sbox[tid] = box;

    const float iou = iou_preds[tid];
    const float stab = (float)g_hi[tid] / fmaxf((float)g_lo[tid], 1.0f);
    const bool valid = (iou > 0.88f) && (stab >= 0.95f);
    skey[tid] = iou;
    skeeporig[tid] = 0;
    __syncthreads();

    if (valid) {
        const int p = atomicAdd(&scnt, 1);
        svidx[p] = tid;
    }
    __syncthreads();
    const int V = scnt;

    // Rank sort (descending score, tie-break by original index ascending)
    if (tid < V) {
        const int orig = svidx[tid];
        const float key = skey[orig];
        int rank = 0;
        for (int j = 0; j < V; ++j) {
            const int oj = svidx[j];
            const float kj = skey[oj];
            rank += (int)((kj > key) | ((kj == key) & (oj < orig)));
        }
        ssorted[rank] = orig;
        skeep[rank] = 1;
    }
    __syncthreads();

    float4 bj = make_float4(0.f, 0.f, 0.f, 0.f);
    float area_j = 0.f;
    if (tid < V) {
        bj = sbox[ssorted[tid]];
        area_j = fmaxf(bj.z - bj.x, 0.f) * fmaxf(bj.w - bj.y, 0.f);
    }

    // Greedy suppression, sorted order. skeep[i] writes only target idx > i,
    // so the single sync at loop top is sufficient ordering.
    for (int i = 0; i < V; ++i) {
        __syncthreads();
        if (!skeep[i]) continue;      // uniform (shared)
        if (tid > i && tid < V && skeep[tid]) {
            const float4 bi = sbox[ssorted[i]];
            const float x0 = fmaxf(bi.x, bj.x);
            const float y0 = fmaxf(bi.y, bj.y);
            const float x1 = fminf(bi.z, bj.z);
            const float y1 = fminf(bi.w, bj.w);
            const float inter = fmaxf(x1 - x0, 0.f) * fmaxf(y1 - y0, 0.f);
            const float area_i = fmaxf(bi.z - bi.x, 0.f) * fmaxf(bi.w - bi.y, 0.f);
            const float u = fmaxf(area_i + area_j - inter, 1e-6f);
            if (inter / u > 0.7f) skeep[tid] = 0;
        }
    }
    __syncthreads();

    if (tid < V && skeep[tid]) skeeporig[ssorted[tid]] = 1;
    __syncthreads();

    const int kept = skeeporig[tid];
    g_gate[tid] = kept ? iou : 0.f;
    if (write_keep) keep_out[tid] = kept ? 1.f : 0.f;
    if (write_boxes) {
        reinterpret_cast<float4*>(boxes_out)[tid] = box;
    }
}

// ---------------------------------------------------------------------------
// Pass 3 (selective): out = sigmoid(logits) * gate[n], ONLY for kept masks
// (~6%). Non-kept masks were already zero-filled by pass 1 — their blocks
// exit immediately. Grid (16, NM), 256 threads, 4 float4 per thread.
// ---------------------------------------------------------------------------
__global__ __launch_bounds__(256) void out_k(const float* __restrict__ logits,
                                             float* __restrict__ out) {
    const int n = blockIdx.y;
    const float g = g_gate[n];
    if (g == 0.f) return;

    const size_t base4 = (size_t)n * (HW / 4) + (size_t)blockIdx.x * 1024;
    const float4* ip = reinterpret_cast<const float4*>(logits) + base4;
    float4* op = reinterpret_cast<float4*>(out) + base4;
    const int tid = threadIdx.x;

#pragma unroll
    for (int k = 0; k < 4; ++k) {
        const float4 v = ip[k * 256 + tid];
        float4 r;
        r.x = g * (1.f / (1.f + __expf(-v.x)));
        r.y = g * (1.f / (1.f + __expf(-v.y)));
        r.z = g * (1.f / (1.f + __expf(-v.z)));
        r.w = g * (1.f / (1.f + __expf(-v.w)));
        op[k * 256 + tid] = r;
    }
}

extern "C" void kernel_launch(void* const* d_in, const int* in_sizes, int n_in,
                              void* d_out, int out_size) {
    const float* logits;
    const float* ioup;
    // Identify inputs by size (mask_logits: 64M elems, iou_preds: 1024)
    if (in_sizes[0] == NM) {
        ioup = (const float*)d_in[0];
        logits = (const float*)d_in[1];
    } else {
        logits = (const float*)d_in[0];
        ioup = (const float*)d_in[1];
    }

    float* out = (float*)d_out;
    const long long main_sz = (long long)NM * HW;
    const int wk = ((long long)out_size >= main_sz + NM) ? 1 : 0;
    const int wb = ((long long)out_size >= main_sz + NM + 4LL * NM) ? 1 : 0;
    float* keep_out = out + (size_t)NM * HW;
    float* boxes_out = keep_out + NM;

    fused_reduce_k<<<NM, 256>>>(logits, out);
    nms_k<<<1, NM>>>(ioup, keep_out, boxes_out, wk, wb);
    out_k<<<dim3(16, NM), 256>>>(logits, out);
}

// round 8
// speedup vs baseline: 1.1114x; 1.0669x over previous
#include <cuda_runtime.h>
#include <math.h>

#define NM 1024
#define HH 256
#define WW 256
#define HW (HH * WW)
#define NBAND 4
#define BAND_F4 4096   // float4s per band (64 rows x 256 cols / 4)

// Per-(mask,band) partial reductions; combined in nms_k. No init needed:
// every slot is overwritten every launch.
__device__ int g_hiP[NM * NBAND];
__device__ int g_loP[NM * NBAND];
__device__ int g_minrP[NM * NBAND];
__device__ int g_maxrP[NM * NBAND];
__device__ int g_mincP[NM * NBAND];
__device__ int g_maxcP[NM * NBAND];
__device__ float g_gate[NM];
__device__ int g_kept[NM];
__device__ int g_nkept;

// ---------------------------------------------------------------------------
// Pass 1 (fused): band-parallel streaming reduction + zero-fill of output.
// Grid 4096 (= NM * 4 bands), 128 threads. Each thread reads 32 float4 and
// stores 32 zero float4s. Zeros are correct for non-kept masks (~95%);
// kept masks are overwritten by pass 3.
//
// idx(local) = it*128 + tid -> col base = (tid&63)*4 fixed per thread,
// row = band*64 + 2*it + (tid>>6). bbox via OR-accumulated 32-bit row(it)
// mask + 4-bit col mask, recovered once with ffs/clz.
// ---------------------------------------------------------------------------
__global__ __launch_bounds__(128) void fused_reduce_k(const float* __restrict__ logits,
                                                      float* __restrict__ out) {
    const int band = blockIdx.x & (NBAND - 1);
    const int n = blockIdx.x >> 2;
    const size_t base4 = (size_t)n * (HW / 4) + (size_t)band * BAND_F4;
    const float4* p = reinterpret_cast<const float4*>(logits) + base4;
    float4* o = reinterpret_cast<float4*>(out) + base4;
    const int tid = threadIdx.x;

    int hi = 0, lo = 0;
    unsigned rowmask = 0u;
    int colbits = 0;
    const float4 z = make_float4(0.f, 0.f, 0.f, 0.f);

#pragma unroll 8
    for (int it = 0; it < 32; ++it) {
        const int idx = it * 128 + tid;
        const float4 v = p[idx];
        o[idx] = z;

        hi += (v.x > 1.f) + (v.y > 1.f) + (v.z > 1.f) + (v.w > 1.f);
        lo += (v.x > -1.f) + (v.y > -1.f) + (v.z > -1.f) + (v.w > -1.f);

        const int b = (int)(v.x > 0.f) | ((int)(v.y > 0.f) << 1) |
                      ((int)(v.z > 0.f) << 2) | ((int)(v.w > 0.f) << 3);
        colbits |= b;
        rowmask |= (unsigned)(b != 0) << it;
    }

    // Recover per-thread bbox
    int minr, maxr, minc, maxc;
    if (rowmask) {
        const int rowoff = (band << 6) + (tid >> 6);
        const int cbase = (tid & 63) << 2;
        const int minIt = __ffs(rowmask) - 1;
        const int maxIt = 31 - __clz(rowmask);
        minr = 2 * minIt + rowoff;
        maxr = 2 * maxIt + rowoff;
        minc = cbase + (__ffs(colbits) - 1);
        maxc = cbase + (31 - __clz((unsigned)colbits));
    } else {
        minr = HH; maxr = -1; minc = WW; maxc = -1;
    }

    // warp reduce
#pragma unroll
    for (int off = 16; off; off >>= 1) {
        hi += __shfl_down_sync(0xffffffffu, hi, off);
        lo += __shfl_down_sync(0xffffffffu, lo, off);
        minr = min(minr, __shfl_down_sync(0xffffffffu, minr, off));
        maxr = max(maxr, __shfl_down_sync(0xffffffffu, maxr, off));
        minc = min(minc, __shfl_down_sync(0xffffffffu, minc, off));
        maxc = max(maxc, __shfl_down_sync(0xffffffffu, maxc, off));
    }

    __shared__ int s[4][6];
    const int w = tid >> 5, l = tid & 31;
    if (l == 0) {
        s[w][0] = hi; s[w][1] = lo; s[w][2] = minr;
        s[w][3] = maxr; s[w][4] = minc; s[w][5] = maxc;
    }
    __syncthreads();
    if (tid == 0) {
        hi = s[0][0] + s[1][0] + s[2][0] + s[3][0];
        lo = s[0][1] + s[1][1] + s[2][1] + s[3][1];
        minr = min(min(s[0][2], s[1][2]), min(s[2][2], s[3][2]));
        maxr = max(max(s[0][3], s[1][3]), max(s[2][3], s[3][3]));
        minc = min(min(s[0][4], s[1][4]), min(s[2][4], s[3][4]));
        maxc = max(max(s[0][5], s[1][5]), max(s[2][5], s[3][5]));
        const int gi = (n << 2) + band;
        g_hiP[gi] = hi; g_loP[gi] = lo;
        g_minrP[gi] = minr; g_maxrP[gi] = maxr;
        g_mincP[gi] = minc; g_maxcP[gi] = maxc;
    }
}

// ---------------------------------------------------------------------------
// Pass 2: combine band partials, validity, boxes, greedy NMS on the valid
// subset (exactly equivalent to reference full-N NMS: invalid masks neither
// keep nor suppress). Rank sort by all threads; suppression by warp 0 only
// (register-resident boxes, __syncwarp ordering — no full-block barriers in
// the O(V) loop). Writes compacted kept list for pass 3.
// ---------------------------------------------------------------------------
__global__ __launch_bounds__(1024) void nms_k(const float* __restrict__ iou_preds,
                                              float* __restrict__ keep_out,
                                              float* __restrict__ boxes_out,
                                              int write_keep, int write_boxes) {
    __shared__ float4 sbox[NM];      // by original index
    __shared__ float4 sboxS[NM];     // by sorted rank
    __shared__ float  sareaS[NM];
    __shared__ float  skey[NM];
    __shared__ int    svidx[NM];
    __shared__ int    ssorted[NM];
    __shared__ int    skeep[NM];
    __shared__ int    skeeporig[NM];
    __shared__ int    scnt;
    __shared__ int    scnt2;

    const int tid = threadIdx.x;
    if (tid == 0) { scnt = 0; scnt2 = 0; }

    // Combine band partials
    const int gi = tid << 2;
    int hi = 0, lo = 0, minr = HH, maxr = -1, minc = WW, maxc = -1;
#pragma unroll
    for (int b = 0; b < NBAND; ++b) {
        hi += g_hiP[gi + b];
        lo += g_loP[gi + b];
        minr = min(minr, g_minrP[gi + b]);
        maxr = max(maxr, g_maxrP[gi + b]);
        minc = min(minc, g_mincP[gi + b]);
        maxc = max(maxc, g_maxcP[gi + b]);
    }

    const bool empty = (maxr < 0);
    const float4 box = empty ? make_float4(0.f, 0.f, 0.f, 0.f)
                             : make_float4((float)minc, (float)minr,
                                           (float)maxc, (float)maxr);
    sbox[tid] = box;

    const float iou = iou_preds[tid];
    const float stab = (float)hi / fmaxf((float)lo, 1.0f);
    const bool valid = (iou > 0.88f) && (stab >= 0.95f);
    skey[tid] = iou;
    skeeporig[tid] = 0;
    __syncthreads();

    if (valid) {
        const int p = atomicAdd(&scnt, 1);
        svidx[p] = tid;
    }
    __syncthreads();
    const int V = scnt;

    // Rank sort (descending score, tie-break by original index ascending)
    if (tid < V) {
        const int orig = svidx[tid];
        const float key = skey[orig];
        int rank = 0;
        for (int j = 0; j < V; ++j) {
            const int oj = svidx[j];
            const float kj = skey[oj];
            rank += (int)((kj > key) | ((kj == key) & (oj < orig)));
        }
        ssorted[rank] = orig;
    }
    __syncthreads();
    if (tid < V) {
        const float4 b = sbox[ssorted[tid]];
        sboxS[tid] = b;
        sareaS[tid] = fmaxf(b.z - b.x, 0.f) * fmaxf(b.w - b.y, 0.f);
        skeep[tid] = 1;
    }
    __syncthreads();

    // Greedy suppression: warp 0 only. Lane owns sorted positions
    // lane, lane+32, ... (slot s -> j = s*32+lane). keep state in a
    // per-lane bitmask + shared skeep for the uniform head test.
    if (tid < 32) {
        const int lane = tid;
        const int nslots = (V + 31) >> 5;
        float4 bx[32];
        float ar[32];
        unsigned kp = 0;
#pragma unroll
        for (int s = 0; s < 32; ++s) {
            if (s >= nslots) break;
            const int j = (s << 5) + lane;
            if (j < V) {
                bx[s] = sboxS[j];
                ar[s] = sareaS[j];
                kp |= 1u << s;
            }
        }
        for (int i = 0; i < V; ++i) {
            if (skeep[i]) {                      // uniform across warp
                const float4 bi = sboxS[i];
                const float area_i = sareaS[i];
#pragma unroll
                for (int s = 0; s < 32; ++s) {
                    if (s >= nslots) break;
                    const int j = (s << 5) + lane;
                    if (j > i && (kp & (1u << s))) {
                        const float x0 = fmaxf(bi.x, bx[s].x);
                        const float y0 = fmaxf(bi.y, bx[s].y);
                        const float x1 = fminf(bi.z, bx[s].z);
                        const float y1 = fminf(bi.w, bx[s].w);
                        const float inter = fmaxf(x1 - x0, 0.f) * fmaxf(y1 - y0, 0.f);
                        const float u = fmaxf(area_i + ar[s] - inter, 1e-6f);
                        if (inter > 0.7f * u) {
                            kp &= ~(1u << s);
                            skeep[j] = 0;
                        }
                    }
                }
            }
            __syncwarp();
        }
    }
    __syncthreads();

    if (tid < V && skeep[tid]) {
        const int orig = ssorted[tid];
        skeeporig[orig] = 1;
        const int p = atomicAdd(&scnt2, 1);
        g_kept[p] = orig;
    }
    __syncthreads();

    const int kept = skeeporig[tid];
    g_gate[tid] = kept ? iou : 0.f;
    if (tid == 0) g_nkept = scnt2;
    if (write_keep) keep_out[tid] = kept ? 1.f : 0.f;
    if (write_boxes) {
        reinterpret_cast<float4*>(boxes_out)[tid] = box;
    }
}

// ---------------------------------------------------------------------------
// Pass 3 (compacted): out = sigmoid(logits) * gate, only over the kept-mask
// list. Grid-stride over 16 chunks per kept mask; each chunk = 1024 float4
// handled by 256 threads x 4 float4. Non-kept masks already zeroed by pass 1.
// ---------------------------------------------------------------------------
__global__ __launch_bounds__(256) void out_k(const float* __restrict__ logits,
                                             float* __restrict__ out) {
    const int nk = g_nkept;
    const int total = nk << 4;
    const int tid = threadIdx.x;

    for (int c = blockIdx.x; c < total; c += gridDim.x) {
        const int m = g_kept[c >> 4];
        const float g = g_gate[m];
        const size_t base4 = (size_t)m * (HW / 4) + (size_t)(c & 15) * 1024;
        const float4* ip = reinterpret_cast<const float4*>(logits) + base4;
        float4* op = reinterpret_cast<float4*>(out) + base4;
#pragma unroll
        for (int k = 0; k < 4; ++k) {
            const float4 v = ip[k * 256 + tid];
            float4 r;
            r.x = g * (1.f / (1.f + __expf(-v.x)));
            r.y = g * (1.f / (1.f + __expf(-v.y)));
            r.z = g * (1.f / (1.f + __expf(-v.z)));
            r.w = g * (1.f / (1.f + __expf(-v.w)));
            op[k * 256 + tid] = r;
        }
    }
}

extern "C" void kernel_launch(void* const* d_in, const int* in_sizes, int n_in,
                              void* d_out, int out_size) {
    const float* logits;
    const float* ioup;
    // Identify inputs by size (mask_logits: 64M elems, iou_preds: 1024)
    if (in_sizes[0] == NM) {
        ioup = (const float*)d_in[0];
        logits = (const float*)d_in[1];
    } else {
        logits = (const float*)d_in[0];
        ioup = (const float*)d_in[1];
    }

    float* out = (float*)d_out;
    const long long main_sz = (long long)NM * HW;
    const int wk = ((long long)out_size >= main_sz + NM) ? 1 : 0;
    const int wb = ((long long)out_size >= main_sz + NM + 4LL * NM) ? 1 : 0;
    float* keep_out = out + (size_t)NM * HW;
    float* boxes_out = keep_out + NM;

    fused_reduce_k<<<NM * NBAND, 128>>>(logits, out);
    nms_k<<<1, NM>>>(ioup, keep_out, boxes_out, wk, wb);
    out_k<<<2048, 256>>>(logits, out);
}

// round 9
// speedup vs baseline: 1.1171x; 1.0051x over previous
#include <cuda_runtime.h>
#include <math.h>

#define NM 1024
#define HH 256
#define WW 256
#define HW (HH * WW)
#define NBAND 4
#define BAND_F4 4096   // float4s per band (64 rows x 256 cols / 4)
#define NBLK (NM * NBAND)

// Per-(mask,band) partial reductions. Every slot overwritten every launch.
__device__ int g_hiP[NM * NBAND];
__device__ int g_loP[NM * NBAND];
__device__ int g_minrP[NM * NBAND];
__device__ int g_maxrP[NM * NBAND];
__device__ int g_mincP[NM * NBAND];
__device__ int g_maxcP[NM * NBAND];
__device__ float g_gate[NM];
__device__ int g_kept[NM];
__device__ int g_nkept;
__device__ unsigned g_done = 0;   // ticket; reset to 0 by the last CTA each launch

// NMS scratch (device globals so the streaming CTAs don't pay smem/regs)
__device__ float4 g_box[NM];
__device__ float4 g_boxS[NM];
__device__ float g_areaS[NM];
__device__ float g_key[NM];
__device__ int g_vidx[NM];
__device__ int g_sorted[NM];

// ---------------------------------------------------------------------------
// Pass 1 (fused): band-parallel streaming reduction + zero-fill of output,
// with NMS executed by the last CTA to finish (threadfence + ticket).
// Grid 4096 (= NM * 4 bands), 128 threads, 32 float4 per thread, .cs hints.
// ---------------------------------------------------------------------------
__global__ __launch_bounds__(128) void fused_reduce_k(const float* __restrict__ logits,
                                                      float* __restrict__ out,
                                                      const float* __restrict__ ioup,
                                                      float* __restrict__ keep_out,
                                                      float* __restrict__ boxes_out,
                                                      int write_keep, int write_boxes) {
    const int band = blockIdx.x & (NBAND - 1);
    const int n = blockIdx.x >> 2;
    const size_t base4 = (size_t)n * (HW / 4) + (size_t)band * BAND_F4;
    const float4* p = reinterpret_cast<const float4*>(logits) + base4;
    float4* o = reinterpret_cast<float4*>(out) + base4;
    const int tid = threadIdx.x;

    int hi = 0, lo = 0;
    unsigned rowmask = 0u;
    int colbits = 0;
    const float4 z = make_float4(0.f, 0.f, 0.f, 0.f);

#pragma unroll 8
    for (int it = 0; it < 32; ++it) {
        const int idx = it * 128 + tid;
        const float4 v = __ldcs(p + idx);
        __stcs(o + idx, z);

        hi += (v.x > 1.f) + (v.y > 1.f) + (v.z > 1.f) + (v.w > 1.f);
        lo += (v.x > -1.f) + (v.y > -1.f) + (v.z > -1.f) + (v.w > -1.f);

        const int b = (int)(v.x > 0.f) | ((int)(v.y > 0.f) << 1) |
                      ((int)(v.z > 0.f) << 2) | ((int)(v.w > 0.f) << 3);
        colbits |= b;
        rowmask |= (unsigned)(b != 0) << it;
    }

    // Recover per-thread bbox (col base fixed per thread; row from it-mask)
    int minr, maxr, minc, maxc;
    if (rowmask) {
        const int rowoff = (band << 6) + (tid >> 6);
        const int cbase = (tid & 63) << 2;
        const int minIt = __ffs(rowmask) - 1;
        const int maxIt = 31 - __clz(rowmask);
        minr = 2 * minIt + rowoff;
        maxr = 2 * maxIt + rowoff;
        minc = cbase + (__ffs(colbits) - 1);
        maxc = cbase + (31 - __clz((unsigned)colbits));
    } else {
        minr = HH; maxr = -1; minc = WW; maxc = -1;
    }

    // warp reduce
#pragma unroll
    for (int off = 16; off; off >>= 1) {
        hi += __shfl_down_sync(0xffffffffu, hi, off);
        lo += __shfl_down_sync(0xffffffffu, lo, off);
        minr = min(minr, __shfl_down_sync(0xffffffffu, minr, off));
        maxr = max(maxr, __shfl_down_sync(0xffffffffu, maxr, off));
        minc = min(minc, __shfl_down_sync(0xffffffffu, minc, off));
        maxc = max(maxc, __shfl_down_sync(0xffffffffu, maxc, off));
    }

    __shared__ int s[4][6];
    __shared__ int sIsLast;
    const int w = tid >> 5, l = tid & 31;
    if (l == 0) {
        s[w][0] = hi; s[w][1] = lo; s[w][2] = minr;
        s[w][3] = maxr; s[w][4] = minc; s[w][5] = maxc;
    }
    __syncthreads();
    if (tid == 0) {
        hi = s[0][0] + s[1][0] + s[2][0] + s[3][0];
        lo = s[0][1] + s[1][1] + s[2][1] + s[3][1];
        minr = min(min(s[0][2], s[1][2]), min(s[2][2], s[3][2]));
        maxr = max(max(s[0][3], s[1][3]), max(s[2][3], s[3][3]));
        minc = min(min(s[0][4], s[1][4]), min(s[2][4], s[3][4]));
        maxc = max(max(s[0][5], s[1][5]), max(s[2][5], s[3][5]));
        const int gi = (n << 2) + band;
        g_hiP[gi] = hi; g_loP[gi] = lo;
        g_minrP[gi] = minr; g_maxrP[gi] = maxr;
        g_mincP[gi] = minc; g_maxcP[gi] = maxc;
        __threadfence();                          // release partials
        const unsigned t = atomicAdd(&g_done, 1u);
        sIsLast = (t == (unsigned)(NBLK - 1));
    }
    __syncthreads();
    if (!sIsLast) return;

    // ======================= LAST CTA: NMS =======================
    __threadfence();                              // acquire others' partials
    __shared__ int scnt, scnt2;
    __shared__ int skeep[NM];                     // by sorted rank
    __shared__ int skeeporig[NM];                 // by original index
    if (tid == 0) { scnt = 0; scnt2 = 0; g_done = 0; }
    __syncthreads();

    // Combine band partials; validity; compaction
    for (int m = tid; m < NM; m += 128) {
        const int gi2 = m << 2;
        int h2 = 0, l2 = 0, mnr = HH, mxr = -1, mnc = WW, mxc = -1;
#pragma unroll
        for (int b = 0; b < NBAND; ++b) {
            h2 += g_hiP[gi2 + b];
            l2 += g_loP[gi2 + b];
            mnr = min(mnr, g_minrP[gi2 + b]);
            mxr = max(mxr, g_maxrP[gi2 + b]);
            mnc = min(mnc, g_mincP[gi2 + b]);
            mxc = max(mxc, g_maxcP[gi2 + b]);
        }
        const bool empty = (mxr < 0);
        const float4 bx = empty ? make_float4(0.f, 0.f, 0.f, 0.f)
                                : make_float4((float)mnc, (float)mnr,
                                              (float)mxc, (float)mxr);
        g_box[m] = bx;
        const float iou = ioup[m];
        g_key[m] = iou;
        skeeporig[m] = 0;
        const float stab = (float)h2 / fmaxf((float)l2, 1.0f);
        if ((iou > 0.88f) && (stab >= 0.95f)) {
            const int pp = atomicAdd(&scnt, 1);
            g_vidx[pp] = m;
        }
    }
    __syncthreads();
    const int V = scnt;

    // Rank sort (descending score, tie-break original index ascending)
    for (int v = tid; v < V; v += 128) {
        const int orig = g_vidx[v];
        const float key = g_key[orig];
        int rank = 0;
        for (int j = 0; j < V; ++j) {
            const int oj = g_vidx[j];
            const float kj = g_key[oj];
            rank += (int)((kj > key) | ((kj == key) & (oj < orig)));
        }
        g_sorted[rank] = orig;
    }
    __syncthreads();
    for (int v = tid; v < V; v += 128) {
        const float4 b = g_box[g_sorted[v]];
        g_boxS[v] = b;
        g_areaS[v] = fmaxf(b.z - b.x, 0.f) * fmaxf(b.w - b.y, 0.f);
        skeep[v] = 1;
    }
    __syncthreads();

    // Greedy suppression, sorted order; skeep[i] head test is uniform after
    // the barrier at the loop top.
    for (int i = 0; i < V; ++i) {
        __syncthreads();
        if (!skeep[i]) continue;
        const float4 bi = g_boxS[i];
        const float area_i = g_areaS[i];
        for (int j = i + 1 + tid; j < V; j += 128) {
            if (skeep[j]) {
                const float4 bj = g_boxS[j];
                const float x0 = fmaxf(bi.x, bj.x);
                const float y0 = fmaxf(bi.y, bj.y);
                const float x1 = fminf(bi.z, bj.z);
                const float y1 = fminf(bi.w, bj.w);
                const float inter = fmaxf(x1 - x0, 0.f) * fmaxf(y1 - y0, 0.f);
                const float u = fmaxf(area_i + g_areaS[j] - inter, 1e-6f);
                if (inter > 0.7f * u) skeep[j] = 0;
            }
        }
    }
    __syncthreads();

    for (int v = tid; v < V; v += 128) {
        if (skeep[v]) {
            const int orig = g_sorted[v];
            skeeporig[orig] = 1;
            const int pp = atomicAdd(&scnt2, 1);
            g_kept[pp] = orig;
        }
    }
    __syncthreads();

    for (int m = tid; m < NM; m += 128) {
        const int kept = skeeporig[m];
        g_gate[m] = kept ? g_key[m] : 0.f;
        if (write_keep) keep_out[m] = kept ? 1.f : 0.f;
        if (write_boxes) reinterpret_cast<float4*>(boxes_out)[m] = g_box[m];
    }
    if (tid == 0) g_nkept = scnt2;
}

// ---------------------------------------------------------------------------
// Pass 2 (compacted): out = sigmoid(logits) * gate, only over the kept-mask
// list (~4%). Grid-stride over 16 chunks per kept mask; 256 threads x 4
// float4 per chunk. Non-kept masks already zeroed by pass 1.
// ---------------------------------------------------------------------------
__global__ __launch_bounds__(256) void out_k(const float* __restrict__ logits,
                                             float* __restrict__ out) {
    const int nk = g_nkept;
    const int total = nk << 4;
    const int tid = threadIdx.x;

    for (int c = blockIdx.x; c < total; c += gridDim.x) {
        const int m = g_kept[c >> 4];
        const float g = g_gate[m];
        const size_t base4 = (size_t)m * (HW / 4) + (size_t)(c & 15) * 1024;
        const float4* ip = reinterpret_cast<const float4*>(logits) + base4;
        float4* op = reinterpret_cast<float4*>(out) + base4;
#pragma unroll
        for (int k = 0; k < 4; ++k) {
            const float4 v = __ldcs(ip + k * 256 + tid);
            float4 r;
            r.x = g * (1.f / (1.f + __expf(-v.x)));
            r.y = g * (1.f / (1.f + __expf(-v.y)));
            r.z = g * (1.f / (1.f + __expf(-v.z)));
            r.w = g * (1.f / (1.f + __expf(-v.w)));
            __stcs(op + k * 256 + tid, r);
        }
    }
}

extern "C" void kernel_launch(void* const* d_in, const int* in_sizes, int n_in,
                              void* d_out, int out_size) {
    const float* logits;
    const float* ioup;
    // Identify inputs by size (mask_logits: 64M elems, iou_preds: 1024)
    if (in_sizes[0] == NM) {
        ioup = (const float*)d_in[0];
        logits = (const float*)d_in[1];
    } else {
        logits = (const float*)d_in[0];
        ioup = (const float*)d_in[1];
    }

    float* out = (float*)d_out;
    const long long main_sz = (long long)NM * HW;
    const int wk = ((long long)out_size >= main_sz + NM) ? 1 : 0;
    const int wb = ((long long)out_size >= main_sz + NM + 4LL * NM) ? 1 : 0;
    float* keep_out = out + (size_t)NM * HW;
    float* boxes_out = keep_out + NM;

    fused_reduce_k<<<NBLK, 128>>>(logits, out, ioup, keep_out, boxes_out, wk, wb);
    out_k<<<2048, 256>>>(logits, out);
}